// round 17
// baseline (speedup 1.0000x reference)
#include <cuda_runtime.h>
#include <mma.h>
#include <math.h>
#include <stdint.h>

using namespace nvcuda;

// ---------------- problem constants ----------------
#define T_LEN 4096
#define DM    2048
#define DI    4096
#define NH    64
#define HD    64
#define DS    128
#define CHUNK 256
#define NC    16
#define CONVD 4352
#define DPROJ 8512
#define ZLD   8576          // padded row stride for zxbcdt (67*128)
#define RMS_EPS 1e-5f

// ---------------- scratch (identical set to passing R11) ----------------
static __device__ float g_zxbcdt[(size_t)T_LEN * ZLD];
static __device__ float g_xbc[(size_t)T_LEN * CONVD];
static __device__ float g_dt[T_LEN * NH];
static __device__ float g_dacs[T_LEN * NH];
static __device__ float g_cb[NC * CHUNK * CHUNK];
static __device__ float g_states[NC * NH * HD * DS];
static __device__ float g_sprev[NC * NH * HD * DS];
static __device__ float g_y[(size_t)T_LEN * DI];

// =====================================================================
// TF32 wmma GEMM: C[M,*] = A[M,K] @ B[Nrows,K]^T (fp32 in/out, tf32 mma)
// CTA 128x128, stage BK=16 (2 x k8 sub-steps), 256 threads / 8 warps
// (warp tile 32x64), double-buffered fp32 smem [128][20] (40 KB total).
// Loader: thread owns row lr = tid>>1, floats half*8..half*8+7 (pure copy).
// =====================================================================
#define SLD 20

__device__ __forceinline__ void gemm_wmma_body(
    const float* __restrict__ A, const float* __restrict__ B,
    float* __restrict__ C, int NrowsB, int K, int ldc)
{
    __shared__ __align__(16) float sA[2][128 * SLD];
    __shared__ __align__(16) float sB[2][128 * SLD];

    const int tid = threadIdx.x;
    const int wid = tid >> 5;
    const int wm  = wid & 3;             // 4 warp-rows of 32
    const int wn  = wid >> 2;            // 2 warp-cols of 64
    const int bm  = blockIdx.y * 128;
    const int bn  = blockIdx.x * 128;
    const int NI  = K >> 4;

    const int lr   = tid >> 1;           // 0..127 loader row
    const int half = tid & 1;            // float4 pair 0 or 1
    const float* Ap = A + (size_t)(bm + lr) * K + half * 8;
    const float* Bp = B + (size_t)(bn + lr) * K + half * 8;
    const bool bvalid = (bn + lr) < NrowsB;
    const int soff = lr * SLD + half * 8;

    wmma::fragment<wmma::accumulator, 16, 16, 8, float> fc[2][4];
#pragma unroll
    for (int mt = 0; mt < 2; ++mt)
#pragma unroll
        for (int nt = 0; nt < 4; ++nt) wmma::fill_fragment(fc[mt][nt], 0.f);

    float4 va0, va1, vb0, vb1;
    const float4 z4 = make_float4(0.f, 0.f, 0.f, 0.f);

#define PF(it) do {                                                    \
        va0 = *(const float4*)(Ap + ((it) << 4));                      \
        va1 = *(const float4*)(Ap + ((it) << 4) + 4);                  \
        if (bvalid) {                                                  \
            vb0 = *(const float4*)(Bp + ((it) << 4));                  \
            vb1 = *(const float4*)(Bp + ((it) << 4) + 4);              \
        } else { vb0 = z4; vb1 = z4; }                                 \
    } while (0)

#define ST(buf) do {                                                   \
        *(float4*)&sA[buf][soff]     = va0;                            \
        *(float4*)&sA[buf][soff + 4] = va1;                            \
        *(float4*)&sB[buf][soff]     = vb0;                            \
        *(float4*)&sB[buf][soff + 4] = vb1;                            \
    } while (0)

    PF(0);
    ST(0);
    __syncthreads();

    for (int it = 0; it < NI; ++it) {
        const int buf = it & 1;
        if (it + 1 < NI) PF(it + 1);

        const float* pA = sA[buf];
        const float* pB = sB[buf];

#pragma unroll
        for (int ks = 0; ks < 2; ++ks) {
            wmma::fragment<wmma::matrix_a, 16, 16, 8, wmma::precision::tf32, wmma::row_major> fa0, fa1;
            wmma::load_matrix_sync(fa0, pA + (wm * 32) * SLD + ks * 8, SLD);
            wmma::load_matrix_sync(fa1, pA + (wm * 32 + 16) * SLD + ks * 8, SLD);
#pragma unroll
            for (int e = 0; e < fa0.num_elements; ++e) {
                fa0.x[e] = wmma::__float_to_tf32(fa0.x[e]);
                fa1.x[e] = wmma::__float_to_tf32(fa1.x[e]);
            }
#pragma unroll
            for (int nt = 0; nt < 4; ++nt) {
                wmma::fragment<wmma::matrix_b, 16, 16, 8, wmma::precision::tf32, wmma::col_major> fb;
                wmma::load_matrix_sync(fb, pB + (wn * 64 + nt * 16) * SLD + ks * 8, SLD);
#pragma unroll
                for (int e = 0; e < fb.num_elements; ++e)
                    fb.x[e] = wmma::__float_to_tf32(fb.x[e]);
                wmma::mma_sync(fc[0][nt], fa0, fb, fc[0][nt]);
                wmma::mma_sync(fc[1][nt], fa1, fb, fc[1][nt]);
            }
        }

        if (it + 1 < NI) {
            ST(buf ^ 1);
            __syncthreads();
        }
    }

#pragma unroll
    for (int mt = 0; mt < 2; ++mt)
#pragma unroll
        for (int nt = 0; nt < 4; ++nt) {
            float* cp = C + (size_t)(bm + wm * 32 + mt * 16) * ldc
                          + (bn + wn * 64 + nt * 16);
            wmma::store_matrix_sync(cp, fc[mt][nt], ldc, wmma::mem_row_major);
        }
#undef PF
#undef ST
}

__global__ __launch_bounds__(256) void gemm_in_kernel(
    const float* __restrict__ hs, const float* __restrict__ w)
{
    gemm_wmma_body(hs, w, g_zxbcdt, DPROJ, DM, ZLD);
}

__global__ __launch_bounds__(256) void gemm_out_kernel(
    const float* __restrict__ w, float* __restrict__ out)
{
    gemm_wmma_body(g_y, w, out, DM, DI, DM);
}

// =====================================================================
// Causal depthwise conv (width 4) + SiLU
// =====================================================================
__global__ void conv_silu_kernel(const float* __restrict__ conv_w,
                                 const float* __restrict__ conv_b)
{
    const int c = blockIdx.x * 256 + threadIdx.x;
    const int t = blockIdx.y;
    float acc = conv_b[c];
#pragma unroll
    for (int k = 0; k < 4; ++k) {
        int tt = t - 3 + k;
        if (tt >= 0)
            acc = fmaf(conv_w[c * 4 + k],
                       g_zxbcdt[(size_t)tt * ZLD + DI + c], acc);
    }
    g_xbc[(size_t)t * CONVD + c] = acc / (1.f + expf(-acc));
}

// =====================================================================
// softplus + per-chunk cumsum of dt*A
// =====================================================================
__global__ void dt_scan_kernel(const float* __restrict__ Av,
                               const float* __restrict__ dtb)
{
    const int c = blockIdx.x >> 6, h = blockIdx.x & 63;   // NH = 64
    const int l = threadIdx.x;
    const int t = c * CHUNK + l;
    float xv = g_zxbcdt[(size_t)t * ZLD + DI + CONVD + h] + dtb[h];
    float dtv = (xv > 15.f) ? xv : log1pf(expf(xv));
    g_dt[t * NH + h] = dtv;

    __shared__ float sb[CHUNK];
    sb[l] = dtv * Av[h];
    __syncthreads();
    for (int off = 1; off < CHUNK; off <<= 1) {
        float v = (l >= off) ? sb[l - off] : 0.f;
        __syncthreads();
        sb[l] += v;
        __syncthreads();
    }
    g_dacs[t * NH + h] = sb[l];
}

// =====================================================================
// CB = C @ B^T per chunk (lower-triangular tiles only)
// =====================================================================
__global__ __launch_bounds__(256) void cb_kernel()
{
    if (blockIdx.x > blockIdx.y) return;
    const int chunk = blockIdx.z;
    const int lt = blockIdx.y * 64, st = blockIdx.x * 64;
    const int tid = threadIdx.x, tx = tid & 15, ty = tid >> 4;
    const int t0 = chunk * CHUNK;
    __shared__ float Cs[16][65];
    __shared__ float Bs[16][65];
    float acc[4][4] = {};
    const int lr = tid >> 2, kc = (tid & 3) * 4;

    for (int k0 = 0; k0 < DS; k0 += 16) {
        __syncthreads();
        float4 cv = *(const float4*)&g_xbc[(size_t)(t0 + lt + lr) * CONVD + DI + DS + k0 + kc];
        Cs[kc + 0][lr] = cv.x; Cs[kc + 1][lr] = cv.y;
        Cs[kc + 2][lr] = cv.z; Cs[kc + 3][lr] = cv.w;
        float4 bv = *(const float4*)&g_xbc[(size_t)(t0 + st + lr) * CONVD + DI + k0 + kc];
        Bs[kc + 0][lr] = bv.x; Bs[kc + 1][lr] = bv.y;
        Bs[kc + 2][lr] = bv.z; Bs[kc + 3][lr] = bv.w;
        __syncthreads();
#pragma unroll
        for (int kk = 0; kk < 16; ++kk) {
            float a[4], b[4];
#pragma unroll
            for (int i = 0; i < 4; ++i) a[i] = Cs[kk][ty * 4 + i];
#pragma unroll
            for (int j = 0; j < 4; ++j) b[j] = Bs[kk][tx * 4 + j];
#pragma unroll
            for (int i = 0; i < 4; ++i)
#pragma unroll
                for (int j = 0; j < 4; ++j)
                    acc[i][j] = fmaf(a[i], b[j], acc[i][j]);
        }
    }
    float* dst = g_cb + chunk * CHUNK * CHUNK;
#pragma unroll
    for (int i = 0; i < 4; ++i)
#pragma unroll
        for (int j = 0; j < 4; ++j)
            dst[(lt + ty * 4 + i) * CHUNK + st + tx * 4 + j] = acc[i][j];
}

// =====================================================================
// y_intra
// =====================================================================
__global__ __launch_bounds__(256) void yintra_kernel()
{
    const int chunk = blockIdx.z, h = blockIdx.y, lt = blockIdx.x * 64;
    const int tid = threadIdx.x, tx = tid & 15, ty = tid >> 4;
    const int t0 = chunk * CHUNK;
    __shared__ float Ws[64][65];
    __shared__ float Xs[64][64];
    __shared__ float dal[64], das[64], dts[64];
    float acc[4][4] = {};
    if (tid < 64) dal[tid] = g_dacs[(t0 + lt + tid) * NH + h];
    const float* cbp = g_cb + chunk * CHUNK * CHUNK;

    for (int st = 0; st <= lt; st += 64) {
        __syncthreads();
        if (tid < 64) {
            das[tid] = g_dacs[(t0 + st + tid) * NH + h];
            dts[tid] = g_dt[(t0 + st + tid) * NH + h];
        }
        __syncthreads();
#pragma unroll
        for (int i = 0; i < 4; ++i) {
            int l = lt + ty * 4 + i;
#pragma unroll
            for (int j = 0; j < 4; ++j) {
                int s = st + tx * 4 + j;
                float w = 0.f;
                if (s <= l)
                    w = cbp[l * CHUNK + s] *
                        expf(dal[ty * 4 + i] - das[tx * 4 + j]) * dts[tx * 4 + j];
                Ws[ty * 4 + i][tx * 4 + j] = w;
            }
        }
#pragma unroll
        for (int rr = 0; rr < 4; ++rr) {
            int srow = rr * 16 + ty;
            *(float4*)&Xs[srow][tx * 4] =
                *(const float4*)&g_xbc[(size_t)(t0 + st + srow) * CONVD + h * HD + tx * 4];
        }
        __syncthreads();
#pragma unroll
        for (int kk = 0; kk < 64; ++kk) {
            float4 b = *(const float4*)&Xs[kk][tx * 4];
#pragma unroll
            for (int i = 0; i < 4; ++i) {
                float a = Ws[ty * 4 + i][kk];
                acc[i][0] = fmaf(a, b.x, acc[i][0]);
                acc[i][1] = fmaf(a, b.y, acc[i][1]);
                acc[i][2] = fmaf(a, b.z, acc[i][2]);
                acc[i][3] = fmaf(a, b.w, acc[i][3]);
            }
        }
    }
#pragma unroll
    for (int i = 0; i < 4; ++i) {
        int t = t0 + lt + ty * 4 + i;
        *(float4*)&g_y[(size_t)t * DI + h * HD + tx * 4] =
            make_float4(acc[i][0], acc[i][1], acc[i][2], acc[i][3]);
    }
}

// =====================================================================
// per-chunk states
// =====================================================================
__global__ __launch_bounds__(256) void states_kernel()
{
    const int h = blockIdx.x, chunk = blockIdx.y;
    const int tid = threadIdx.x, tx = tid & 15, ty = tid >> 4;
    const int t0 = chunk * CHUNK;
    __shared__ float Xt[32][64];
    __shared__ float Bt[32][128];
    __shared__ float coef[32];
    float acc[4][8] = {};
    const float dacs_last = g_dacs[(t0 + CHUNK - 1) * NH + h];

    for (int l0 = 0; l0 < CHUNK; l0 += 32) {
        __syncthreads();
        if (tid < 32) {
            int t = t0 + l0 + tid;
            coef[tid] = g_dt[t * NH + h] * expf(dacs_last - g_dacs[t * NH + h]);
        }
        {
            int r = tid >> 3, c = (tid & 7) * 8;
            *(float4*)&Xt[r][c] =
                *(const float4*)&g_xbc[(size_t)(t0 + l0 + r) * CONVD + h * HD + c];
            *(float4*)&Xt[r][c + 4] =
                *(const float4*)&g_xbc[(size_t)(t0 + l0 + r) * CONVD + h * HD + c + 4];
            int c2 = (tid & 7) * 16;
#pragma unroll
            for (int q = 0; q < 4; ++q)
                *(float4*)&Bt[r][c2 + q * 4] =
                    *(const float4*)&g_xbc[(size_t)(t0 + l0 + r) * CONVD + DI + c2 + q * 4];
        }
        __syncthreads();
#pragma unroll
        for (int kk = 0; kk < 32; ++kk) {
            float ck = coef[kk];
            float a[4];
#pragma unroll
            for (int i = 0; i < 4; ++i) a[i] = Xt[kk][ty * 4 + i] * ck;
            float4 b0 = *(const float4*)&Bt[kk][tx * 8];
            float4 b1 = *(const float4*)&Bt[kk][tx * 8 + 4];
            float b[8] = {b0.x, b0.y, b0.z, b0.w, b1.x, b1.y, b1.z, b1.w};
#pragma unroll
            for (int i = 0; i < 4; ++i)
#pragma unroll
                for (int j = 0; j < 8; ++j)
                    acc[i][j] = fmaf(a[i], b[j], acc[i][j]);
        }
    }
    float* dst = g_states + (size_t)(chunk * NH + h) * HD * DS;
#pragma unroll
    for (int i = 0; i < 4; ++i) {
        int p = ty * 4 + i;
#pragma unroll
        for (int j = 0; j < 8; j += 4)
            *(float4*)&dst[p * DS + tx * 8 + j] =
                make_float4(acc[i][j], acc[i][j + 1], acc[i][j + 2], acc[i][j + 3]);
    }
}

// =====================================================================
// cross-chunk scan
// =====================================================================
__global__ void scan_kernel()
{
    const int idx = blockIdx.x * blockDim.x + threadIdx.x;
    const int h = idx >> 13;            // HD*DS = 8192
    float S = 0.f;
#pragma unroll
    for (int c = 0; c < NC; ++c) {
        g_sprev[(size_t)c * (NH * HD * DS) + idx] = S;
        float cd = expf(g_dacs[(c * CHUNK + CHUNK - 1) * NH + h]);
        S = fmaf(cd, S, g_states[(size_t)c * (NH * HD * DS) + idx]);
    }
}

// =====================================================================
// y_inter + gate
// =====================================================================
__global__ __launch_bounds__(256) void yinter_kernel(const float* __restrict__ Dp)
{
    const int chunk = blockIdx.z, h = blockIdx.y, lt = blockIdx.x * 64;
    const int tid = threadIdx.x, tx = tid & 15, ty = tid >> 4;
    const int t0 = chunk * CHUNK;
    __shared__ float Cs[16][65];
    __shared__ float Ss[16][65];
    float acc[4][4] = {};
    const float* sp = g_sprev + (size_t)(chunk * NH + h) * HD * DS;
    const int lr = tid >> 2, nc = (tid & 3) * 4;

    for (int n0 = 0; n0 < DS; n0 += 16) {
        __syncthreads();
        {
            float4 cv = *(const float4*)&g_xbc[(size_t)(t0 + lt + lr) * CONVD + DI + DS + n0 + nc];
            Cs[nc + 0][lr] = cv.x; Cs[nc + 1][lr] = cv.y;
            Cs[nc + 2][lr] = cv.z; Cs[nc + 3][lr] = cv.w;
            float4 sv = *(const float4*)&sp[lr * DS + n0 + nc];
            Ss[nc + 0][lr] = sv.x; Ss[nc + 1][lr] = sv.y;
            Ss[nc + 2][lr] = sv.z; Ss[nc + 3][lr] = sv.w;
        }
        __syncthreads();
#pragma unroll
        for (int kk = 0; kk < 16; ++kk) {
            float a[4], b[4];
#pragma unroll
            for (int i = 0; i < 4; ++i) a[i] = Cs[kk][ty * 4 + i];
#pragma unroll
            for (int j = 0; j < 4; ++j) b[j] = Ss[kk][tx * 4 + j];
#pragma unroll
            for (int i = 0; i < 4; ++i)
#pragma unroll
                for (int j = 0; j < 4; ++j)
                    acc[i][j] = fmaf(a[i], b[j], acc[i][j]);
        }
    }

    const float Dh = Dp[h];
#pragma unroll
    for (int i = 0; i < 4; ++i) {
        int t = t0 + lt + ty * 4 + i;
        float esc = expf(g_dacs[t * NH + h]);
#pragma unroll
        for (int j = 0; j < 4; ++j) {
            int col = h * HD + tx * 4 + j;
            float x = g_xbc[(size_t)t * CONVD + col];
            float z = g_zxbcdt[(size_t)t * ZLD + col];
            float yv = g_y[(size_t)t * DI + col] + acc[i][j] * esc + x * Dh;
            float gate = z / (1.f + expf(-z));
            g_y[(size_t)t * DI + col] = yv * gate;
        }
    }
}

// =====================================================================
// RMSNorm in place
// =====================================================================
__global__ void rmsnorm_kernel(const float* __restrict__ norm_w)
{
    const int t = blockIdx.x;
    float* row = g_y + (size_t)t * DI;
    float ss = 0.f;
    for (int c = threadIdx.x; c < DI; c += 256) {
        float v = row[c];
        ss = fmaf(v, v, ss);
    }
    __shared__ float red[256];
    red[threadIdx.x] = ss;
    __syncthreads();
    for (int o = 128; o > 0; o >>= 1) {
        if (threadIdx.x < o) red[threadIdx.x] += red[threadIdx.x + o];
        __syncthreads();
    }
    const float r = rsqrtf(red[0] / (float)DI + RMS_EPS);
    for (int c = threadIdx.x; c < DI; c += 256)
        row[c] = row[c] * r * norm_w[c];
}

// =====================================================================
// launch
// =====================================================================
extern "C" void kernel_launch(void* const* d_in, const int* in_sizes, int n_in,
                              void* d_out, int out_size)
{
    const float* hs   = (const float*)d_in[0];
    const float* win  = (const float*)d_in[1];
    const float* cw   = (const float*)d_in[2];
    const float* cbv  = (const float*)d_in[3];
    const float* Av   = (const float*)d_in[4];
    const float* Dp   = (const float*)d_in[5];
    const float* dtb  = (const float*)d_in[6];
    const float* nw   = (const float*)d_in[7];
    const float* wout = (const float*)d_in[8];
    float* out = (float*)d_out;

    gemm_in_kernel<<<dim3(ZLD / 128, T_LEN / 128), 256>>>(hs, win);
    conv_silu_kernel<<<dim3(CONVD / 256, T_LEN), 256>>>(cw, cbv);
    dt_scan_kernel<<<NC * NH, CHUNK>>>(Av, dtb);
    cb_kernel<<<dim3(4, 4, NC), 256>>>();
    yintra_kernel<<<dim3(4, NH, NC), 256>>>();
    states_kernel<<<dim3(NH, NC), 256>>>();
    scan_kernel<<<(NH * HD * DS) / 256, 256>>>();
    yinter_kernel<<<dim3(4, NH, NC), 256>>>(Dp);
    rmsnorm_kernel<<<T_LEN, 256>>>(nw);
    gemm_out_kernel<<<dim3(DM / 128, T_LEN / 128), 256>>>(wout, out);
}